// round 2
// baseline (speedup 1.0000x reference)
#include <cuda_runtime.h>
#include <math.h>

// Problem constants
#define Bb 2
#define Dd 256
#define Hh 8
#define Tt 128
#define Ff 64
#define Cc 512
#define TEc 512
#define Ss 128
#define NROW (Bb * Tt * Ss)   // 32768 rows of act/R
#define BT (Bb * Tt)          // 256

// Scratch (no cudaMalloc allowed)
__device__ float g_time_proj[BT * Cc];      // 256 x 512
__device__ float g_table[256 * Cc];         // 255 used x 512
__device__ float g_act[NROW * Cc];          // 64 MB
__device__ float g_R[NROW * Cc];            // 64 MB

// ---------------------------------------------------------------------------
// K0: distance-embedding projection table: table[d+127][c]
//     = log1p(max(d,0))*w_dist[0,c] + log1p(max(-d,0))*w_dist[1,c]
//       + (d==0)*w_dist[2,c] + b_dist[c]
// ---------------------------------------------------------------------------
__global__ void k_table(const float* __restrict__ w_dist,
                        const float* __restrict__ b_dist) {
    int dd = blockIdx.x;        // 0..254  -> d = dd-127
    int c  = threadIdx.x;       // 0..511
    float d  = (float)(dd - 127);
    float e0 = log1pf(fmaxf(d, 0.f));
    float e1 = log1pf(fmaxf(-d, 0.f));
    float e2 = (dd == 127) ? 1.f : 0.f;
    g_table[dd * Cc + c] = e0 * w_dist[c] + e1 * w_dist[Cc + c]
                         + e2 * w_dist[2 * Cc + c] + b_dist[c];
}

// ---------------------------------------------------------------------------
// K1: time_proj[bt][c] = temb[bt,:] @ w_time[:,c] + b_time[c]
//     8 rows per block, 512 threads (1 col each), w_time read once per block
// ---------------------------------------------------------------------------
__global__ void k_time_proj(const float* __restrict__ temb,
                            const float* __restrict__ w_time,
                            const float* __restrict__ b_time) {
    int r0 = blockIdx.x * 8;
    int c  = threadIdx.x;
    __shared__ float s[8][TEc];
    for (int i = threadIdx.x; i < 8 * TEc; i += blockDim.x)
        s[i / TEc][i % TEc] = temb[(r0 + i / TEc) * TEc + (i % TEc)];
    __syncthreads();
    float acc[8];
#pragma unroll
    for (int r = 0; r < 8; r++) acc[r] = b_time[c];
    for (int k = 0; k < TEc; k++) {
        float w = w_time[k * Cc + c];
#pragma unroll
        for (int r = 0; r < 8; r++) acc[r] += s[r][k] * w;
    }
#pragma unroll
    for (int r = 0; r < 8; r++) g_time_proj[(r0 + r) * Cc + c] = acc[r];
}

// ---------------------------------------------------------------------------
// K2: act[row][c] = silu(time_proj[bt][c] + table[pd[row]+127][c])
//     row = (b*T + t)*S + s ; bt = row >> 7 ; vectorized float4
// ---------------------------------------------------------------------------
__global__ void k_act(const int* __restrict__ pd) {
    int i   = blockIdx.x * blockDim.x + threadIdx.x;  // over NROW*Cc/4
    int row = i >> 7;        // / (Cc/4 = 128)
    int c4  = i & 127;
    int d   = pd[row];
    int bt  = row >> 7;      // / S
    float4 tp = ((const float4*)g_time_proj)[bt * 128 + c4];
    float4 tb = ((const float4*)g_table)[(d + 127) * 128 + c4];
    float4 v;
    float x;
    x = tp.x + tb.x; v.x = x / (1.f + __expf(-x));
    x = tp.y + tb.y; v.y = x / (1.f + __expf(-x));
    x = tp.z + tb.z; v.z = x / (1.f + __expf(-x));
    x = tp.w + tb.w; v.w = x / (1.f + __expf(-x));
    ((float4*)g_act)[i] = v;
}

// ---------------------------------------------------------------------------
// K3: R = act @ w_out + b_out   (M=32768, N=512, K=512)
//     128x128 block tile, BK=16, 256 threads, 8x8 per-thread register tile
// ---------------------------------------------------------------------------
__global__ __launch_bounds__(256) void k_rgemm(const float* __restrict__ W,
                                               const float* __restrict__ bias) {
    __shared__ float As[16][128];   // [k][m]
    __shared__ float Bs[16][128];   // [k][n]
    int n0 = blockIdx.x * 128;
    int m0 = blockIdx.y * 128;
    int t  = threadIdx.x;
    int tx = t & 15, ty = t >> 4;
    float acc[8][8];
#pragma unroll
    for (int i = 0; i < 8; i++)
#pragma unroll
        for (int j = 0; j < 8; j++) acc[i][j] = 0.f;

    const float* Aptr = g_act + (size_t)m0 * Cc;

    for (int k0 = 0; k0 < Cc; k0 += 16) {
#pragma unroll
        for (int i = 0; i < 2; i++) {   // A: 128x16 (transposed store)
            int m  = (t >> 2) + i * 64;
            int k4 = (t & 3) * 4;
            float4 v = *(const float4*)(Aptr + (size_t)m * Cc + k0 + k4);
            As[k4 + 0][m] = v.x; As[k4 + 1][m] = v.y;
            As[k4 + 2][m] = v.z; As[k4 + 3][m] = v.w;
        }
#pragma unroll
        for (int i = 0; i < 2; i++) {   // B: 16x128 (direct)
            int k  = (t >> 5) + i * 8;
            int n4 = (t & 31) * 4;
            *(float4*)&Bs[k][n4] = *(const float4*)(W + (size_t)(k0 + k) * Cc + n0 + n4);
        }
        __syncthreads();
#pragma unroll
        for (int k = 0; k < 16; k++) {
            float a[8], bv[8];
            *(float4*)(a)     = *(const float4*)&As[k][ty * 8];
            *(float4*)(a + 4) = *(const float4*)&As[k][ty * 8 + 4];
            *(float4*)(bv)     = *(const float4*)&Bs[k][tx * 8];
            *(float4*)(bv + 4) = *(const float4*)&Bs[k][tx * 8 + 4];
#pragma unroll
            for (int i = 0; i < 8; i++)
#pragma unroll
                for (int j = 0; j < 8; j++) acc[i][j] += a[i] * bv[j];
        }
        __syncthreads();
    }
#pragma unroll
    for (int i = 0; i < 8; i++) {
        int m = m0 + ty * 8 + i;
#pragma unroll
        for (int j = 0; j < 8; j += 4) {
            int n = n0 + tx * 8 + j;
            float4 v;
            v.x = acc[i][j + 0] + bias[n + 0];
            v.y = acc[i][j + 1] + bias[n + 1];
            v.z = acc[i][j + 2] + bias[n + 2];
            v.w = acc[i][j + 3] + bias[n + 3];
            *(float4*)(g_R + (size_t)m * Cc + n) = v;
        }
    }
}

// ---------------------------------------------------------------------------
// K4: out[b,d,h,t,s] = sum_f qk[b,d,h,t,f] * R[b,t,s,h*F+f]
//     Batched GEMM: per (b,h,t): (D=256 x F=64) @ (S=128 x F=64)^T
//     128x128 tile (2 d-tiles per batch), BK=32, 8x8 per thread
// ---------------------------------------------------------------------------
__global__ __launch_bounds__(256) void k_qkgemm(const float* __restrict__ qk,
                                                float* __restrict__ out) {
    __shared__ float As[32][128];   // [f][d]
    __shared__ float Bs[32][128];   // [f][s]
    int batch = blockIdx.y;              // b*H*T + h*T + t
    int b  = batch >> 10;                // /(H*T)=1024
    int h  = (batch >> 7) & 7;
    int tt = batch & 127;
    int d0 = blockIdx.x * 128;

    size_t baseA   = ((((size_t)b * Dd + d0) * Hh + h) * Tt + tt) * Ff;
    size_t strideA = (size_t)Hh * Tt * Ff;      // 65536
    size_t baseB   = (((size_t)b * Tt + tt) * Ss) * Cc + (size_t)h * Ff;
    size_t baseO   = ((((size_t)b * Dd + d0) * Hh + h) * Tt + tt) * Ss;
    size_t strideO = (size_t)Hh * Tt * Ss;      // 131072

    int t  = threadIdx.x;
    int tx = t & 15, ty = t >> 4;
    float acc[8][8];
#pragma unroll
    for (int i = 0; i < 8; i++)
#pragma unroll
        for (int j = 0; j < 8; j++) acc[i][j] = 0.f;

    for (int k0 = 0; k0 < Ff; k0 += 32) {
#pragma unroll
        for (int i = 0; i < 4; i++) {
            int dl = (t >> 3) + i * 32;     // row (d for A, s for B)
            int f4 = (t & 7) * 4;
            float4 v = *(const float4*)(qk + baseA + (size_t)dl * strideA + k0 + f4);
            As[f4 + 0][dl] = v.x; As[f4 + 1][dl] = v.y;
            As[f4 + 2][dl] = v.z; As[f4 + 3][dl] = v.w;
            float4 w = *(const float4*)(g_R + baseB + (size_t)dl * Cc + k0 + f4);
            Bs[f4 + 0][dl] = w.x; Bs[f4 + 1][dl] = w.y;
            Bs[f4 + 2][dl] = w.z; Bs[f4 + 3][dl] = w.w;
        }
        __syncthreads();
#pragma unroll
        for (int k = 0; k < 32; k++) {
            float a[8], bv[8];
            *(float4*)(a)      = *(const float4*)&As[k][ty * 8];
            *(float4*)(a + 4)  = *(const float4*)&As[k][ty * 8 + 4];
            *(float4*)(bv)     = *(const float4*)&Bs[k][tx * 8];
            *(float4*)(bv + 4) = *(const float4*)&Bs[k][tx * 8 + 4];
#pragma unroll
            for (int i = 0; i < 8; i++)
#pragma unroll
                for (int j = 0; j < 8; j++) acc[i][j] += a[i] * bv[j];
        }
        __syncthreads();
    }
#pragma unroll
    for (int i = 0; i < 8; i++) {
        size_t orow = baseO + (size_t)(ty * 8 + i) * strideO;
#pragma unroll
        for (int j = 0; j < 8; j += 4) {
            int s = tx * 8 + j;
            float4 v;
            v.x = acc[i][j + 0]; v.y = acc[i][j + 1];
            v.z = acc[i][j + 2]; v.w = acc[i][j + 3];
            *(float4*)(out + orow + s) = v;
        }
    }
}

// ---------------------------------------------------------------------------
extern "C" void kernel_launch(void* const* d_in, const int* in_sizes, int n_in,
                              void* d_out, int out_size) {
    const float* qk     = (const float*)d_in[0];
    const float* temb   = (const float*)d_in[1];
    const int*   pd     = (const int*)d_in[2];
    const float* w_dist = (const float*)d_in[3];
    const float* b_dist = (const float*)d_in[4];
    const float* w_time = (const float*)d_in[5];
    const float* b_time = (const float*)d_in[6];
    const float* w_out  = (const float*)d_in[7];
    const float* b_out  = (const float*)d_in[8];
    float* out = (float*)d_out;

    k_table<<<255, 512>>>(w_dist, b_dist);
    k_time_proj<<<BT / 8, 512>>>(temb, w_time, b_time);
    k_act<<<(NROW * Cc / 4) / 256, 256>>>(pd);
    k_rgemm<<<dim3(Cc / 128, NROW / 128), 256>>>(w_out, b_out);
    k_qkgemm<<<dim3(Dd / 128, Bb * Hh * Tt), 256>>>(qk, out);
}

// round 3
// speedup vs baseline: 2.1419x; 2.1419x over previous
#include <cuda_runtime.h>
#include <math.h>

// Problem constants
#define Bb 2
#define Dd 256
#define Hh 8
#define Tt 128
#define Ff 64
#define Cc 512
#define TEc 512
#define Ss 128
#define NROW (Bb * Tt * Ss)   // 32768 rows of act/R
#define BT (Bb * Tt)          // 256

// Scratch (no cudaMalloc allowed)
__device__ float g_time_proj[BT * Cc];      // 256 x 512
__device__ float g_table[256 * Cc];         // 255 used x 512
__device__ float g_act[NROW * Cc];          // 64 MB
__device__ float g_R[NROW * Cc];            // 64 MB

// ---------------------------------------------------------------------------
// tf32 helpers
// ---------------------------------------------------------------------------
__device__ __forceinline__ unsigned f2tf(float x) {
    unsigned r;
    asm("cvt.rna.tf32.f32 %0, %1;" : "=r"(r) : "f"(x));
    return r;
}

__device__ __forceinline__ void mma_tf32(float* c, const unsigned* a, const unsigned* b) {
    asm volatile(
        "mma.sync.aligned.m16n8k8.row.col.f32.tf32.tf32.f32 "
        "{%0,%1,%2,%3}, {%4,%5,%6,%7}, {%8,%9}, {%0,%1,%2,%3};"
        : "+f"(c[0]), "+f"(c[1]), "+f"(c[2]), "+f"(c[3])
        : "r"(a[0]), "r"(a[1]), "r"(a[2]), "r"(a[3]),
          "r"(b[0]), "r"(b[1]));
}

// ---------------------------------------------------------------------------
// K0: distance-embedding projection table
// ---------------------------------------------------------------------------
__global__ void k_table(const float* __restrict__ w_dist,
                        const float* __restrict__ b_dist) {
    int dd = blockIdx.x;        // 0..254  -> d = dd-127
    int c  = threadIdx.x;       // 0..511
    float d  = (float)(dd - 127);
    float e0 = log1pf(fmaxf(d, 0.f));
    float e1 = log1pf(fmaxf(-d, 0.f));
    float e2 = (dd == 127) ? 1.f : 0.f;
    g_table[dd * Cc + c] = e0 * w_dist[c] + e1 * w_dist[Cc + c]
                         + e2 * w_dist[2 * Cc + c] + b_dist[c];
}

// ---------------------------------------------------------------------------
// K1: time_proj = temb @ w_time + b_time  (256x512x512, tiny)
// ---------------------------------------------------------------------------
__global__ void k_time_proj(const float* __restrict__ temb,
                            const float* __restrict__ w_time,
                            const float* __restrict__ b_time) {
    int r0 = blockIdx.x * 8;
    int c  = threadIdx.x;
    __shared__ float s[8][TEc];
    for (int i = threadIdx.x; i < 8 * TEc; i += blockDim.x)
        s[i / TEc][i % TEc] = temb[(r0 + i / TEc) * TEc + (i % TEc)];
    __syncthreads();
    float acc[8];
#pragma unroll
    for (int r = 0; r < 8; r++) acc[r] = b_time[c];
    for (int k = 0; k < TEc; k++) {
        float w = w_time[k * Cc + c];
#pragma unroll
        for (int r = 0; r < 8; r++) acc[r] += s[r][k] * w;
    }
#pragma unroll
    for (int r = 0; r < 8; r++) g_time_proj[(r0 + r) * Cc + c] = acc[r];
}

// ---------------------------------------------------------------------------
// K2: act[row][c] = silu(time_proj[bt][c] + table[pd[row]+127][c])
// ---------------------------------------------------------------------------
__global__ void k_act(const int* __restrict__ pd) {
    int i   = blockIdx.x * blockDim.x + threadIdx.x;
    int row = i >> 7;
    int c4  = i & 127;
    int d   = pd[row];
    int bt  = row >> 7;
    float4 tp = ((const float4*)g_time_proj)[bt * 128 + c4];
    float4 tb = ((const float4*)g_table)[(d + 127) * 128 + c4];
    float4 v;
    float x;
    x = tp.x + tb.x; v.x = x / (1.f + __expf(-x));
    x = tp.y + tb.y; v.y = x / (1.f + __expf(-x));
    x = tp.z + tb.z; v.z = x / (1.f + __expf(-x));
    x = tp.w + tb.w; v.w = x / (1.f + __expf(-x));
    ((float4*)g_act)[i] = v;
}

// ---------------------------------------------------------------------------
// K3: R = act @ w_out + b_out  (M=32768, N=512, K=512) — tf32 tensor cores
//     128x128 block, 8 warps (2x4), warp 64x32 = 4x4 m16n8k8 frags, BK=32
// ---------------------------------------------------------------------------
#define RG_LDA 36
#define RG_LDB 136
__global__ __launch_bounds__(256) void k_rgemm_tc(const float* __restrict__ W,
                                                  const float* __restrict__ bias) {
    __shared__ unsigned As[128 * RG_LDA];   // [m][k]  pad->conflict-free
    __shared__ unsigned Bs[32 * RG_LDB];    // [k][n]
    int n0 = blockIdx.x * 128;
    int m0 = blockIdx.y * 128;
    int t = threadIdx.x;
    int warp = t >> 5, lane = t & 31;
    int wm = (warp >> 2) * 64, wn = (warp & 3) * 32;
    int grp = lane >> 2, tig = lane & 3;
    float acc[4][4][4];
#pragma unroll
    for (int mi = 0; mi < 4; mi++)
#pragma unroll
        for (int ni = 0; ni < 4; ni++)
#pragma unroll
            for (int q = 0; q < 4; q++) acc[mi][ni][q] = 0.f;

    const float* Aptr = g_act + (size_t)m0 * Cc;

    for (int k0 = 0; k0 < Cc; k0 += 32) {
        // A: 128x32 tile (1024 float4, 4 per thread)
#pragma unroll
        for (int i = 0; i < 4; i++) {
            int f = t + 256 * i;
            int m = f >> 3, kp = (f & 7) * 4;
            float4 v = *(const float4*)(Aptr + (size_t)m * Cc + k0 + kp);
            unsigned* dst = &As[m * RG_LDA + kp];
            dst[0] = f2tf(v.x); dst[1] = f2tf(v.y);
            dst[2] = f2tf(v.z); dst[3] = f2tf(v.w);
        }
        // B: 32x128 tile
#pragma unroll
        for (int i = 0; i < 4; i++) {
            int kk = (t >> 5) + 8 * i;
            int nn = (t & 31) * 4;
            float4 v = *(const float4*)(W + (size_t)(k0 + kk) * Cc + n0 + nn);
            unsigned* dst = &Bs[kk * RG_LDB + nn];
            dst[0] = f2tf(v.x); dst[1] = f2tf(v.y);
            dst[2] = f2tf(v.z); dst[3] = f2tf(v.w);
        }
        __syncthreads();
#pragma unroll
        for (int k8 = 0; k8 < 32; k8 += 8) {
            unsigned a[4][4], b[4][2];
#pragma unroll
            for (int mi = 0; mi < 4; mi++) {
                int r = wm + mi * 16 + grp;
                a[mi][0] = As[r * RG_LDA + k8 + tig];
                a[mi][1] = As[(r + 8) * RG_LDA + k8 + tig];
                a[mi][2] = As[r * RG_LDA + k8 + tig + 4];
                a[mi][3] = As[(r + 8) * RG_LDA + k8 + tig + 4];
            }
#pragma unroll
            for (int ni = 0; ni < 4; ni++) {
                int n = wn + ni * 8 + grp;
                b[ni][0] = Bs[(k8 + tig) * RG_LDB + n];
                b[ni][1] = Bs[(k8 + tig + 4) * RG_LDB + n];
            }
#pragma unroll
            for (int mi = 0; mi < 4; mi++)
#pragma unroll
                for (int ni = 0; ni < 4; ni++)
                    mma_tf32(acc[mi][ni], a[mi], b[ni]);
        }
        __syncthreads();
    }
    // epilogue: +bias, store float2 pairs
#pragma unroll
    for (int mi = 0; mi < 4; mi++) {
        int r = m0 + wm + mi * 16 + grp;
#pragma unroll
        for (int ni = 0; ni < 4; ni++) {
            int n = n0 + wn + ni * 8 + tig * 2;
            float2 bv = *(const float2*)(bias + n);
            float2 v0, v1;
            v0.x = acc[mi][ni][0] + bv.x; v0.y = acc[mi][ni][1] + bv.y;
            v1.x = acc[mi][ni][2] + bv.x; v1.y = acc[mi][ni][3] + bv.y;
            *(float2*)(g_R + (size_t)r * Cc + n) = v0;
            *(float2*)(g_R + (size_t)(r + 8) * Cc + n) = v1;
        }
    }
}

// ---------------------------------------------------------------------------
// K4: out[b,d,h,t,s] = sum_f qk[b,d,h,t,f] * R[b,t,s,hF+f] — tf32 TCs
//     Per (b,h,t,dblk): M=128(d), N=128(s), K=64(f). BK=32 (2 iters).
// ---------------------------------------------------------------------------
#define QG_LDA 36
#define QG_LDB 36
__global__ __launch_bounds__(256) void k_qkgemm_tc(const float* __restrict__ qk,
                                                   float* __restrict__ out) {
    __shared__ unsigned As[128 * QG_LDA];   // [d][f]
    __shared__ unsigned Bs[128 * QG_LDB];   // [s][f]
    int bid = blockIdx.x;
    int dblk = bid & 1;
    int batch = bid >> 1;             // b*H*T + h*T + t
    int b = batch >> 10;
    int h = (batch >> 7) & 7;
    int tt = batch & 127;
    int d0 = dblk * 128;

    size_t baseA = ((((size_t)b * Dd + d0) * Hh + h) * Tt + tt) * Ff;
    size_t baseB = (((size_t)b * Tt + tt) * Ss) * Cc + (size_t)h * Ff;
    size_t baseO = ((((size_t)b * Dd + d0) * Hh + h) * Tt + tt) * Ss;
    const size_t strideA = (size_t)Hh * Tt * Ff;   // 65536
    const size_t strideO = (size_t)Hh * Tt * Ss;   // 131072

    int t = threadIdx.x;
    int warp = t >> 5, lane = t & 31;
    int wm = (warp >> 2) * 64, wn = (warp & 3) * 32;
    int grp = lane >> 2, tig = lane & 3;
    float acc[4][4][4];
#pragma unroll
    for (int mi = 0; mi < 4; mi++)
#pragma unroll
        for (int ni = 0; ni < 4; ni++)
#pragma unroll
            for (int q = 0; q < 4; q++) acc[mi][ni][q] = 0.f;

    for (int k0 = 0; k0 < Ff; k0 += 32) {
        // A: 128 rows (d) x 32 f, strided rows
#pragma unroll
        for (int i = 0; i < 4; i++) {
            int f = t + 256 * i;
            int m = f >> 3, kp = (f & 7) * 4;
            float4 v = *(const float4*)(qk + baseA + (size_t)m * strideA + k0 + kp);
            unsigned* dst = &As[m * QG_LDA + kp];
            dst[0] = f2tf(v.x); dst[1] = f2tf(v.y);
            dst[2] = f2tf(v.z); dst[3] = f2tf(v.w);
        }
        // B: 128 rows (s) x 32 f from g_R
#pragma unroll
        for (int i = 0; i < 4; i++) {
            int f = t + 256 * i;
            int m = f >> 3, kp = (f & 7) * 4;
            float4 v = *(const float4*)(g_R + baseB + (size_t)m * Cc + k0 + kp);
            unsigned* dst = &Bs[m * QG_LDB + kp];
            dst[0] = f2tf(v.x); dst[1] = f2tf(v.y);
            dst[2] = f2tf(v.z); dst[3] = f2tf(v.w);
        }
        __syncthreads();
#pragma unroll
        for (int k8 = 0; k8 < 32; k8 += 8) {
            unsigned a[4][4], b2[4][2];
#pragma unroll
            for (int mi = 0; mi < 4; mi++) {
                int r = wm + mi * 16 + grp;
                a[mi][0] = As[r * QG_LDA + k8 + tig];
                a[mi][1] = As[(r + 8) * QG_LDA + k8 + tig];
                a[mi][2] = As[r * QG_LDA + k8 + tig + 4];
                a[mi][3] = As[(r + 8) * QG_LDA + k8 + tig + 4];
            }
#pragma unroll
            for (int ni = 0; ni < 4; ni++) {
                int n = wn + ni * 8 + grp;     // n indexes s (rows of Bs)
                b2[ni][0] = Bs[n * QG_LDB + k8 + tig];
                b2[ni][1] = Bs[n * QG_LDB + k8 + tig + 4];
            }
#pragma unroll
            for (int mi = 0; mi < 4; mi++)
#pragma unroll
                for (int ni = 0; ni < 4; ni++)
                    mma_tf32(acc[mi][ni], a[mi], b2[ni]);
        }
        __syncthreads();
    }
    // epilogue
#pragma unroll
    for (int mi = 0; mi < 4; mi++) {
        int r = wm + mi * 16 + grp;
#pragma unroll
        for (int ni = 0; ni < 4; ni++) {
            int n = wn + ni * 8 + tig * 2;
            float2 v0, v1;
            v0.x = acc[mi][ni][0]; v0.y = acc[mi][ni][1];
            v1.x = acc[mi][ni][2]; v1.y = acc[mi][ni][3];
            *(float2*)(out + baseO + (size_t)r * strideO + n) = v0;
            *(float2*)(out + baseO + (size_t)(r + 8) * strideO + n) = v1;
        }
    }
}

// ---------------------------------------------------------------------------
extern "C" void kernel_launch(void* const* d_in, const int* in_sizes, int n_in,
                              void* d_out, int out_size) {
    const float* qk     = (const float*)d_in[0];
    const float* temb   = (const float*)d_in[1];
    const int*   pd     = (const int*)d_in[2];
    const float* w_dist = (const float*)d_in[3];
    const float* b_dist = (const float*)d_in[4];
    const float* w_time = (const float*)d_in[5];
    const float* b_time = (const float*)d_in[6];
    const float* w_out  = (const float*)d_in[7];
    const float* b_out  = (const float*)d_in[8];
    float* out = (float*)d_out;

    k_table<<<255, 512>>>(w_dist, b_dist);
    k_time_proj<<<BT / 8, 512>>>(temb, w_time, b_time);
    k_act<<<(NROW * Cc / 4) / 256, 256>>>(pd);
    k_rgemm_tc<<<dim3(Cc / 128, NROW / 128), 256>>>(w_out, b_out);
    k_qkgemm_tc<<<Bb * Hh * Tt * 2, 256>>>(qk, out);
}

// round 5
// speedup vs baseline: 2.6121x; 1.2195x over previous
#include <cuda_runtime.h>
#include <math.h>

// Problem constants
#define Bb 2
#define Dd 256
#define Hh 8
#define Tt 128
#define Ff 64
#define Cc 512
#define TEc 512
#define Ss 128
#define NROW (Bb * Tt * Ss)   // 32768
#define BT (Bb * Tt)          // 256

// Scratch (no cudaMalloc allowed)
__device__ float    g_time_proj[BT * Cc];
__device__ float    g_table[256 * Cc];
__device__ unsigned g_act[NROW * Cc];   // tf32 bits
__device__ unsigned g_R[NROW * Cc];     // tf32 bits
__device__ unsigned g_Wtf[Cc * Cc];     // w_out as tf32 bits

// ---------------------------------------------------------------------------
// helpers
// ---------------------------------------------------------------------------
__device__ __forceinline__ unsigned f2tf(float x) {
    unsigned r;
    asm("cvt.rna.tf32.f32 %0, %1;" : "=r"(r) : "f"(x));
    return r;
}
__device__ __forceinline__ float tanh_fast(float x) {
    float y;
    asm("tanh.approx.f32 %0, %1;" : "=f"(y) : "f"(x));
    return y;
}
__device__ __forceinline__ float silu_fast(float x) {
    return x * (0.5f * tanh_fast(0.5f * x) + 0.5f);
}
__device__ __forceinline__ void mma_tf32(float* c, const unsigned* a, const unsigned* b) {
    asm volatile(
        "mma.sync.aligned.m16n8k8.row.col.f32.tf32.tf32.f32 "
        "{%0,%1,%2,%3}, {%4,%5,%6,%7}, {%8,%9}, {%0,%1,%2,%3};"
        : "+f"(c[0]), "+f"(c[1]), "+f"(c[2]), "+f"(c[3])
        : "r"(a[0]), "r"(a[1]), "r"(a[2]), "r"(a[3]),
          "r"(b[0]), "r"(b[1]));
}
__device__ __forceinline__ void cp16(unsigned sdst, const void* gsrc) {
    asm volatile("cp.async.cg.shared.global [%0], [%1], 16;\n"
                 :: "r"(sdst), "l"(gsrc));
}
#define CP_COMMIT() asm volatile("cp.async.commit_group;\n" ::: "memory")
#define CP_WAIT(n)  asm volatile("cp.async.wait_group %0;\n" :: "n"(n) : "memory")

// ---------------------------------------------------------------------------
// K0: distance table (includes b_dist)
// ---------------------------------------------------------------------------
__global__ void k_table(const float* __restrict__ w_dist,
                        const float* __restrict__ b_dist) {
    int dd = blockIdx.x;        // 0..254 -> d = dd-127
    int c  = threadIdx.x;
    float d  = (float)(dd - 127);
    float e0 = log1pf(fmaxf(d, 0.f));
    float e1 = log1pf(fmaxf(-d, 0.f));
    float e2 = (dd == 127) ? 1.f : 0.f;
    g_table[dd * Cc + c] = e0 * w_dist[c] + e1 * w_dist[Cc + c]
                         + e2 * w_dist[2 * Cc + c] + b_dist[c];
}

// ---------------------------------------------------------------------------
// K0b: convert w_out to tf32 bits
// ---------------------------------------------------------------------------
__global__ void k_wconv(const float* __restrict__ W) {
    int i = blockIdx.x * blockDim.x + threadIdx.x;
    g_Wtf[i] = f2tf(W[i]);
}

// ---------------------------------------------------------------------------
// K1: time_proj = temb @ w_time + b_time (tiny)
// ---------------------------------------------------------------------------
__global__ void k_time_proj(const float* __restrict__ temb,
                            const float* __restrict__ w_time,
                            const float* __restrict__ b_time) {
    int r0 = blockIdx.x * 8;
    int c  = threadIdx.x;
    __shared__ float s[8][TEc];
    for (int i = threadIdx.x; i < 8 * TEc; i += blockDim.x)
        s[i / TEc][i % TEc] = temb[(r0 + i / TEc) * TEc + (i % TEc)];
    __syncthreads();
    float acc[8];
#pragma unroll
    for (int r = 0; r < 8; r++) acc[r] = b_time[c];
    for (int k = 0; k < TEc; k++) {
        float w = w_time[k * Cc + c];
#pragma unroll
        for (int r = 0; r < 8; r++) acc[r] += s[r][k] * w;
    }
#pragma unroll
    for (int r = 0; r < 8; r++) g_time_proj[(r0 + r) * Cc + c] = acc[r];
}

// ---------------------------------------------------------------------------
// K2: act = tf32(silu(time_proj + table[d]))  — 1 MUFU/element via tanh
// ---------------------------------------------------------------------------
__global__ void k_act(const int* __restrict__ pd) {
    int i   = blockIdx.x * blockDim.x + threadIdx.x;
    int row = i >> 7;
    int c4  = i & 127;
    int d   = pd[row];
    int bt  = row >> 7;
    float4 tp = ((const float4*)g_time_proj)[bt * 128 + c4];
    float4 tb = ((const float4*)g_table)[(d + 127) * 128 + c4];
    uint4 v;
    v.x = f2tf(silu_fast(tp.x + tb.x));
    v.y = f2tf(silu_fast(tp.y + tb.y));
    v.z = f2tf(silu_fast(tp.z + tb.z));
    v.w = f2tf(silu_fast(tp.w + tb.w));
    ((uint4*)g_act)[i] = v;
}

// ---------------------------------------------------------------------------
// K3: R = act @ w_out + b_out (M=32768,N=512,K=512), tf32 TC,
//     cp.async 3-stage pipeline, one sync per k-iter. Writes g_R as tf32.
// ---------------------------------------------------------------------------
#define RG_LDA 36
#define RG_LDB 136
#define RG_AS  (128 * RG_LDA)   // u32 per A stage
#define RG_BS  (32 * RG_LDB)    // u32 per B stage
#define RG_NIT 16               // 512 / 32

__global__ __launch_bounds__(256) void k_rgemm_tc(const float* __restrict__ bias) {
    extern __shared__ unsigned sh[];
    unsigned* As = sh;                 // [3][RG_AS]
    unsigned* Bs = sh + 3 * RG_AS;     // [3][RG_BS]
    unsigned sh_u = (unsigned)__cvta_generic_to_shared(sh);
    unsigned As_u = sh_u;
    unsigned Bs_u = sh_u + 3 * RG_AS * 4;

    int n0 = blockIdx.x * 128;
    int m0 = blockIdx.y * 128;
    int t = threadIdx.x;
    int warp = t >> 5, lane = t & 31;
    int wm = (warp >> 2) * 64, wn = (warp & 3) * 32;
    int grp = lane >> 2, tig = lane & 3;

    float acc[4][4][4];
#pragma unroll
    for (int mi = 0; mi < 4; mi++)
#pragma unroll
        for (int ni = 0; ni < 4; ni++)
#pragma unroll
            for (int q = 0; q < 4; q++) acc[mi][ni][q] = 0.f;

    // per-thread load coords (4 x 16B each for A and B)
    int am[4], ak[4], bk[4], bn[4];
#pragma unroll
    for (int i = 0; i < 4; i++) {
        int f = t + 256 * i;
        am[i] = f >> 3;  ak[i] = (f & 7) * 4;
        bk[i] = f >> 5;  bn[i] = (f & 31) * 4;
    }

    auto prefetch = [&](int st, int k0) {
#pragma unroll
        for (int i = 0; i < 4; i++) {
            cp16(As_u + (st * RG_AS + am[i] * RG_LDA + ak[i]) * 4,
                 g_act + (size_t)(m0 + am[i]) * Cc + k0 + ak[i]);
            cp16(Bs_u + (st * RG_BS + bk[i] * RG_LDB + bn[i]) * 4,
                 g_Wtf + (size_t)(k0 + bk[i]) * Cc + n0 + bn[i]);
        }
    };

    prefetch(0, 0);  CP_COMMIT();
    prefetch(1, 32); CP_COMMIT();

    for (int it = 0; it < RG_NIT; it++) {
        CP_WAIT(1);
        __syncthreads();
        if (it + 2 < RG_NIT) prefetch((it + 2) % 3, (it + 2) * 32);
        CP_COMMIT();

        const unsigned* A = As + (it % 3) * RG_AS;
        const unsigned* B = Bs + (it % 3) * RG_BS;
#pragma unroll
        for (int k8 = 0; k8 < 32; k8 += 8) {
            unsigned a[4][4], b[4][2];
#pragma unroll
            for (int mi = 0; mi < 4; mi++) {
                int r = wm + mi * 16 + grp;
                a[mi][0] = A[r * RG_LDA + k8 + tig];
                a[mi][1] = A[(r + 8) * RG_LDA + k8 + tig];
                a[mi][2] = A[r * RG_LDA + k8 + tig + 4];
                a[mi][3] = A[(r + 8) * RG_LDA + k8 + tig + 4];
            }
#pragma unroll
            for (int ni = 0; ni < 4; ni++) {
                int n = wn + ni * 8 + grp;
                b[ni][0] = B[(k8 + tig) * RG_LDB + n];
                b[ni][1] = B[(k8 + tig + 4) * RG_LDB + n];
            }
#pragma unroll
            for (int mi = 0; mi < 4; mi++)
#pragma unroll
                for (int ni = 0; ni < 4; ni++)
                    mma_tf32(acc[mi][ni], a[mi], b[ni]);
        }
        __syncthreads();   // protect stage (it%3) before it is refilled at it+1? no:
                           // refill of stage (it+2)%3 happens next iter AFTER the
                           // wait+sync there; this sync guards stage reuse distance.
    }

    // epilogue: +bias, convert to tf32 bits for qkgemm
#pragma unroll
    for (int mi = 0; mi < 4; mi++) {
        int r = m0 + wm + mi * 16 + grp;
#pragma unroll
        for (int ni = 0; ni < 4; ni++) {
            int n = n0 + wn + ni * 8 + tig * 2;
            float2 bv = *(const float2*)(bias + n);
            uint2 v0, v1;
            v0.x = f2tf(acc[mi][ni][0] + bv.x); v0.y = f2tf(acc[mi][ni][1] + bv.y);
            v1.x = f2tf(acc[mi][ni][2] + bv.x); v1.y = f2tf(acc[mi][ni][3] + bv.y);
            *(uint2*)(g_R + (size_t)r * Cc + n) = v0;
            *(uint2*)(g_R + (size_t)(r + 8) * Cc + n) = v1;
        }
    }
}

// ---------------------------------------------------------------------------
// K4: out[b,d,h,t,s] = sum_f qk[..f] * R[..f]  — whole K=64 staged once,
//     single sync, B via cp.async from tf32 g_R, A via LDG+cvt.
// ---------------------------------------------------------------------------
#define QG_LD  68
#define QG_SZ  (128 * QG_LD)
__global__ __launch_bounds__(256) void k_qkgemm_tc(const float* __restrict__ qk,
                                                   float* __restrict__ out) {
    extern __shared__ unsigned sh[];
    unsigned* As = sh;            // [128][68]  (d x f)
    unsigned* Bs = sh + QG_SZ;    // [128][68]  (s x f)
    unsigned Bs_u = (unsigned)__cvta_generic_to_shared(Bs);

    int bid = blockIdx.x;
    int dblk = bid & 1;
    int batch = bid >> 1;             // b*H*T + h*T + t
    int b = batch >> 10;
    int h = (batch >> 7) & 7;
    int tt = batch & 127;
    int d0 = dblk * 128;

    size_t baseA = ((((size_t)b * Dd + d0) * Hh + h) * Tt + tt) * Ff;
    size_t baseB = (((size_t)b * Tt + tt) * Ss) * Cc + (size_t)h * Ff;
    size_t baseO = ((((size_t)b * Dd + d0) * Hh + h) * Tt + tt) * Ss;
    const size_t strideA = (size_t)Hh * Tt * Ff;   // 65536
    const size_t strideO = (size_t)Hh * Tt * Ss;   // 131072

    int t = threadIdx.x;
    int warp = t >> 5, lane = t & 31;
    int wm = (warp >> 2) * 64, wn = (warp & 3) * 32;
    int grp = lane >> 2, tig = lane & 3;

    // B tile async (128 rows x 64 f = 8 x 16B per thread)
#pragma unroll
    for (int i = 0; i < 8; i++) {
        int f = t + 256 * i;
        int m = f >> 4, kp = (f & 15) * 4;
        cp16(Bs_u + (m * QG_LD + kp) * 4, g_R + baseB + (size_t)m * Cc + kp);
    }
    CP_COMMIT();

    float acc[4][4][4];
#pragma unroll
    for (int mi = 0; mi < 4; mi++)
#pragma unroll
        for (int ni = 0; ni < 4; ni++)
#pragma unroll
            for (int q = 0; q < 4; q++) acc[mi][ni][q] = 0.f;

    // A tile: LDG float4 + cvt + STS (overlaps with B cp.async)
#pragma unroll
    for (int i = 0; i < 8; i++) {
        int f = t + 256 * i;
        int m = f >> 4, kp = (f & 15) * 4;
        float4 v = *(const float4*)(qk + baseA + (size_t)m * strideA + kp);
        unsigned* dst = &As[m * QG_LD + kp];
        dst[0] = f2tf(v.x); dst[1] = f2tf(v.y);
        dst[2] = f2tf(v.z); dst[3] = f2tf(v.w);
    }

    CP_WAIT(0);
    __syncthreads();

#pragma unroll
    for (int k8 = 0; k8 < 64; k8 += 8) {
        unsigned a[4][4], b2[4][2];
#pragma unroll
        for (int mi = 0; mi < 4; mi++) {
            int r = wm + mi * 16 + grp;
            a[mi][0] = As[r * QG_LD + k8 + tig];
            a[mi][1] = As[(r + 8) * QG_LD + k8 + tig];
            a[mi][2] = As[r * QG_LD + k8 + tig + 4];
            a[mi][3] = As[(r + 8) * QG_LD + k8 + tig + 4];
        }
#pragma unroll
        for (int ni = 0; ni < 4; ni++) {
            int n = wn + ni * 8 + grp;
            b2[ni][0] = Bs[n * QG_LD + k8 + tig];
            b2[ni][1] = Bs[n * QG_LD + k8 + tig + 4];
        }
#pragma unroll
        for (int mi = 0; mi < 4; mi++)
#pragma unroll
            for (int ni = 0; ni < 4; ni++)
                mma_tf32(acc[mi][ni], a[mi], b2[ni]);
    }

#pragma unroll
    for (int mi = 0; mi < 4; mi++) {
        int r = wm + mi * 16 + grp;
#pragma unroll
        for (int ni = 0; ni < 4; ni++) {
            int n = wn + ni * 8 + tig * 2;
            float2 v0, v1;
            v0.x = acc[mi][ni][0]; v0.y = acc[mi][ni][1];
            v1.x = acc[mi][ni][2]; v1.y = acc[mi][ni][3];
            *(float2*)(out + baseO + (size_t)r * strideO + n) = v0;
            *(float2*)(out + baseO + (size_t)(r + 8) * strideO + n) = v1;
        }
    }
}

// ---------------------------------------------------------------------------
extern "C" void kernel_launch(void* const* d_in, const int* in_sizes, int n_in,
                              void* d_out, int out_size) {
    const float* qk     = (const float*)d_in[0];
    const float* temb   = (const float*)d_in[1];
    const int*   pd     = (const int*)d_in[2];
    const float* w_dist = (const float*)d_in[3];
    const float* b_dist = (const float*)d_in[4];
    const float* w_time = (const float*)d_in[5];
    const float* b_time = (const float*)d_in[6];
    const float* w_out  = (const float*)d_in[7];
    const float* b_out  = (const float*)d_in[8];
    float* out = (float*)d_out;

    const int rg_smem = 3 * (RG_AS + RG_BS) * 4;   // 107,520 B
    const int qg_smem = 2 * QG_SZ * 4;             //  69,632 B
    cudaFuncSetAttribute(k_rgemm_tc, cudaFuncAttributeMaxDynamicSharedMemorySize, rg_smem);
    cudaFuncSetAttribute(k_qkgemm_tc, cudaFuncAttributeMaxDynamicSharedMemorySize, qg_smem);

    k_table<<<255, 512>>>(w_dist, b_dist);
    k_wconv<<<Cc * Cc / 512, 512>>>(w_out);
    k_time_proj<<<BT / 8, 512>>>(temb, w_time, b_time);
    k_act<<<(NROW * Cc / 4) / 256, 256>>>(pd);
    k_rgemm_tc<<<dim3(Cc / 128, NROW / 128), 256, rg_smem>>>(b_out);
    k_qkgemm_tc<<<Bb * Hh * Tt * 2, 256, qg_smem>>>(qk, out);
}